// round 15
// baseline (speedup 1.0000x reference)
#include <cuda_runtime.h>
#include <cuda_fp16.h>

// ---------------- problem constants ----------------
#define BATCH    8192
#define IN_FEAT  512
#define OUT_FEAT 512
#define GK       13                       // GRID_SIZE + K
#define KTOT     (IN_FEAT + IN_FEAT*GK)   // 7168
#define ROWBYTES (KTOT * 2)               // 14336 bytes per fp16 row
#define KCHUNK   64                       // fp16 elems per stage chunk = 128B
#define NCHUNKS  (KTOT / KCHUNK)          // 112
#define TILE_M   128
#define TILE_N   128
#define STAGES   3
#define N_MTILES (BATCH / TILE_M)         // 64
#define N_NTILES (OUT_FEAT / TILE_N)      // 4
#define ACT_PER_TILE (TILE_M / 2)         // 64 act blocks per m-tile
#define GRP      (ACT_PER_TILE + N_NTILES) // 68 blocks per tile group

// k' layout (permuted, transparent to the GEMM):
//   k' in [0,512)     -> silu(x_i),           i = k'
//   k' in [512,7168)  -> basis_g(x_i), g = (k'-512)/512, i = (k'-512)%512
// g_wk uses the identical permutation, so the dot product is unchanged.

// ---------------- scratch (device globals; no allocation allowed) ------
__device__ __half g_act[(size_t)BATCH * KTOT];     // 117 MB activation matrix
__device__ __half g_wk [(size_t)OUT_FEAT * KTOT];  // 7.3 MB packed weights

// ---------------- dataflow counters (self-resetting each launch) -------
__device__ int g_w_rdy;                    // 512 weight blocks arrive
__device__ int g_tile_rdy[N_MTILES];       // 64 act blocks per tile arrive
__device__ int g_tile_done[N_MTILES];      // 4 GEMM CTAs per tile retire
__device__ int g_all_done;                 // 256 GEMM CTAs retire

// ---------------- helpers ----------------
__device__ __forceinline__ unsigned smem_u32(const void* p) {
    unsigned a;
    asm("{ .reg .u64 t; cvta.to.shared.u64 t, %1; cvt.u32.u64 %0, t; }"
        : "=r"(a) : "l"(p));
    return a;
}
__device__ __forceinline__ void cp16(unsigned saddr, const void* gaddr) {
    asm volatile("cp.async.cg.shared.global [%0], [%1], 16;"
                 :: "r"(saddr), "l"(gaddr));
}
__device__ __forceinline__ void cp_commit() {
    asm volatile("cp.async.commit_group;");
}
template <int N>
__device__ __forceinline__ void cp_wait() {
    asm volatile("cp.async.wait_group %0;" :: "n"(N));
}
__device__ __forceinline__ void ldx4(unsigned* r, unsigned addr) {
    asm volatile("ldmatrix.sync.aligned.m8n8.x4.shared.b16 {%0,%1,%2,%3}, [%4];"
                 : "=r"(r[0]), "=r"(r[1]), "=r"(r[2]), "=r"(r[3]) : "r"(addr));
}
__device__ __forceinline__ void mma16816(float* d, const unsigned* a,
                                         unsigned b0, unsigned b1) {
    asm volatile(
        "mma.sync.aligned.m16n8k16.row.col.f32.f16.f16.f32 "
        "{%0,%1,%2,%3}, {%4,%5,%6,%7}, {%8,%9}, {%0,%1,%2,%3};"
        : "+f"(d[0]), "+f"(d[1]), "+f"(d[2]), "+f"(d[3])
        : "r"(a[0]), "r"(a[1]), "r"(a[2]), "r"(a[3]), "r"(b0), "r"(b1));
}

// ================= fused kernel =================
// bid < 512                      : weight block o = bid
// bid >= 512, group t = (bid-512)/68, sub = (bid-512)%68:
//     sub < 64  -> act block, rows [t*128 + 2*sub, +2)
//     sub >= 64 -> GEMM CTA, m-tile t, n-tile sub-64
#define A_BYTES     (TILE_M * KCHUNK * 2)        // 16384
#define B_BYTES     (TILE_N * KCHUNK * 2)        // 16384
#define STAGE_BYTES (A_BYTES + B_BYTES)          // 32768
#define SMEM_TOTAL  (STAGES * STAGE_BYTES)       // 98304

__global__ void __launch_bounds__(256, 2)
kan_fused(const float* __restrict__ x,
          const float* __restrict__ base_w,
          const float* __restrict__ spline_w,
          const float* __restrict__ bias,
          float* __restrict__ out) {
    extern __shared__ char smem[];
    int tid = threadIdx.x;
    int bid = blockIdx.x;

    // ================== weight producer ==================
    if (bid < OUT_FEAT) {
        __half* s = (__half*)smem;             // IN_FEAT*14 halves = 14336 B
        int o = bid;
        const float* bw = base_w + (size_t)o * IN_FEAT;
        __half* dstb = g_wk + (size_t)o * KTOT;
#pragma unroll
        for (int i = tid; i < IN_FEAT; i += 256)
            dstb[i] = __float2half_rn(bw[i]);

        const float* sw = spline_w + (size_t)o * (IN_FEAT * GK);
        for (int idx = tid; idx < IN_FEAT * GK; idx += 256) {
            int i = idx / GK, g = idx % GK;    // coalesced read
            s[i * 14 + g] = __float2half_rn(sw[idx]);
        }
        __syncthreads();

        __half* dsts = dstb + IN_FEAT;
        for (int idx = tid; idx < IN_FEAT * GK; idx += 256) {
            int g = idx >> 9, i = idx & 511;   // k' = g*512 + i (coalesced write)
            dsts[idx] = s[i * 14 + g];
        }
        __threadfence();
        __syncthreads();
        if (tid == 0) atomicAdd(&g_w_rdy, 1);
        return;
    }

    int r    = bid - OUT_FEAT;
    int tile = r / GRP;
    int sub  = r % GRP;

    // ================== activation producer (2 rows) ==================
    if (sub < ACT_PER_TILE) {
        __half* s = (__half*)smem;             // 2*KTOT halves = 28672 B
        int r0 = tile * TILE_M + sub * 2;

        // phase 1: zero the row image
        int4* z = (int4*)s;
#pragma unroll
        for (int k = 0; k < 7; ++k)
            z[tid + k * 256] = make_int4(0, 0, 0, 0);
        __syncthreads();

        // phase 2: scatter silu + nonzero cubic B-spline weights
        int row = tid >> 7;                    // 0..1
        int i0  = (tid & 127) << 2;            // 0..508
        float4 xv = *(const float4*)(x + (size_t)(r0 + row) * IN_FEAT + i0);
        __half* srow = s + row * KTOT;
        float xs[4] = { xv.x, xv.y, xv.z, xv.w };
#pragma unroll
        for (int e = 0; e < 4; ++e) {
            float v = xs[e];
            srow[i0 + e] = __float2half_rn(v / (1.0f + __expf(-v)));   // silu
            float t = (v + 3.2f) * 2.5f;       // knots -3.2 + 0.4j
            if (t >= 0.0f && t < 16.0f) {
                int j = (int)t;
                float u  = t - (float)j;
                float um = 1.0f - u;
                float u2 = u * u, u3 = u2 * u;
                float um3 = um * um * um;
                const float c6 = 1.0f / 6.0f;
                float wv[4];
                wv[0] = um3 * c6;
                wv[1] = (3.0f * u3 - 6.0f * u2 + 4.0f) * c6;
                wv[2] = (-3.0f * u3 + 3.0f * u2 + 3.0f * u + 1.0f) * c6;
                wv[3] = u3 * c6;
                int g0 = j - 3;
#pragma unroll
                for (int d = 0; d < 4; ++d) {
                    int g = g0 + d;
                    if (g >= 0 && g < GK)      // reference truncates edge bases
                        srow[IN_FEAT + (g << 9) + i0 + e] = __float2half_rn(wv[d]);
                }
            }
        }
        __syncthreads();

        // phase 3: coalesced copy-out
        const int4* src = (const int4*)s;
        int4* dst = (int4*)(g_act + (size_t)r0 * KTOT);
#pragma unroll
        for (int k = 0; k < 7; ++k)
            dst[tid + k * 256] = src[tid + k * 256];

        __threadfence();
        __syncthreads();
        if (tid == 0) atomicAdd(&g_tile_rdy[tile], 1);
        return;
    }

    // ================== GEMM consumer CTA ==================
    {
        int m_base = tile * TILE_M;
        int n_base = (sub - ACT_PER_TILE) * TILE_N;

        // wait for weights + this tile's activations
        if (tid == 0) {
            while (*(volatile int*)&g_w_rdy < OUT_FEAT) {}
            while (*(volatile int*)&g_tile_rdy[tile] < ACT_PER_TILE) {}
            __threadfence();
        }
        __syncthreads();

        unsigned sb = smem_u32(smem);
        int w    = tid >> 5;
        int lane = tid & 31;
        int wm   = w >> 2;          // 0..1  (M, 64 rows each)
        int wn   = w & 3;           // 0..3  (N, 32 cols each)

        // ---- cp.async loader precompute: 4 groups of 16B per thread/tile ----
        unsigned so[4];
        const char* ga[4];
        const char* gb[4];
#pragma unroll
        for (int q = 0; q < 4; ++q) {
            int g   = tid + q * 256;          // 0..1023
            int rw  = g >> 3;                 // 0..127
            int c8  = g & 7;                  // 16B column
            so[q] = (unsigned)((rw << 7) + (((unsigned)c8 ^ (rw & 7)) << 4));
            ga[q] = (const char*)g_act + (size_t)(m_base + rw) * ROWBYTES + c8 * 16;
            gb[q] = (const char*)g_wk  + (size_t)(n_base + rw) * ROWBYTES + c8 * 16;
        }

        // ---- ldmatrix per-lane precompute ----
        int lrow = lane & 15;
        unsigned lh = (unsigned)(lane >> 4);
        unsigned arow[4], abit[4];
#pragma unroll
        for (int mt = 0; mt < 4; ++mt) {
            int rr = wm * 64 + mt * 16 + lrow;
            arow[mt] = (unsigned)(rr << 7);
            abit[mt] = (unsigned)(rr & 7);
        }
        unsigned brow[2], bbit[2];
#pragma unroll
        for (int bt = 0; bt < 2; ++bt) {
            int rr = wn * 32 + bt * 16 + lrow;
            brow[bt] = (unsigned)(rr << 7);
            bbit[bt] = (unsigned)(rr & 7);
        }

        float acc[4][4][4];
#pragma unroll
        for (int mt = 0; mt < 4; ++mt)
#pragma unroll
            for (int nt = 0; nt < 4; ++nt)
#pragma unroll
                for (int e = 0; e < 4; ++e) acc[mt][nt][e] = 0.0f;

        // ---- prologue: chunks 0,1 into stages 0,1 ----
#pragma unroll
        for (int p = 0; p < 2; ++p) {
            unsigned base = sb + p * STAGE_BYTES;
            size_t koff = (size_t)p * 128;
#pragma unroll
            for (int q = 0; q < 4; ++q) cp16(base + so[q], ga[q] + koff);
#pragma unroll
            for (int q = 0; q < 4; ++q) cp16(base + A_BYTES + so[q], gb[q] + koff);
            cp_commit();
        }

        int s_cur = 0, s_nxt = 2;
        for (int c = 0; c < NCHUNKS; ++c) {
            if (c < NCHUNKS - 1) cp_wait<1>(); else cp_wait<0>();
            __syncthreads();

            if (c + 2 < NCHUNKS) {
                unsigned base = sb + s_nxt * STAGE_BYTES;
                size_t koff = (size_t)(c + 2) * 128;
#pragma unroll
                for (int q = 0; q < 4; ++q) cp16(base + so[q], ga[q] + koff);
#pragma unroll
                for (int q = 0; q < 4; ++q) cp16(base + A_BYTES + so[q], gb[q] + koff);
                cp_commit();
            }

            unsigned Ab = sb + s_cur * STAGE_BYTES;
            unsigned Bb = Ab + A_BYTES;
#pragma unroll
            for (int kt = 0; kt < 4; ++kt) {
                unsigned kc8 = (unsigned)(kt * 2) + lh;
                unsigned af[4][4];
#pragma unroll
                for (int mt = 0; mt < 4; ++mt)
                    ldx4(af[mt], Ab + arow[mt] + ((kc8 ^ abit[mt]) << 4));
                unsigned bf[2][4];
#pragma unroll
                for (int bt = 0; bt < 2; ++bt)
                    ldx4(bf[bt], Bb + brow[bt] + ((kc8 ^ bbit[bt]) << 4));
#pragma unroll
                for (int mt = 0; mt < 4; ++mt)
#pragma unroll
                    for (int nt = 0; nt < 4; ++nt)
                        mma16816(acc[mt][nt], af[mt],
                                 bf[nt >> 1][nt & 1], bf[nt >> 1][(nt & 1) + 2]);
            }

            s_cur = (s_cur == STAGES - 1) ? 0 : s_cur + 1;
            s_nxt = (s_nxt == STAGES - 1) ? 0 : s_nxt + 1;
        }

        // ---- epilogue: bias add + store (f32) ----
        int r0base = m_base + wm * 64 + (lane >> 2);
        int colb   = n_base + wn * 32 + ((lane & 3) << 1);
        float2 bs[4];
#pragma unroll
        for (int nt = 0; nt < 4; ++nt)
            bs[nt] = *(const float2*)(bias + colb + nt * 8);
#pragma unroll
        for (int mt = 0; mt < 4; ++mt) {
            int r0 = r0base + mt * 16;
            int r1 = r0 + 8;
#pragma unroll
            for (int nt = 0; nt < 4; ++nt) {
                int col = colb + nt * 8;
                float2 v0 = { acc[mt][nt][0] + bs[nt].x, acc[mt][nt][1] + bs[nt].y };
                float2 v1 = { acc[mt][nt][2] + bs[nt].x, acc[mt][nt][3] + bs[nt].y };
                *(float2*)(out + (size_t)r0 * OUT_FEAT + col) = v0;
                *(float2*)(out + (size_t)r1 * OUT_FEAT + col) = v1;
            }
        }

        // ---- retire: reset counters for the next (graph-replayed) launch ----
        if (tid == 0) {
            int d = atomicAdd(&g_tile_done[tile], 1);
            if (d == N_NTILES - 1) {
                g_tile_done[tile] = 0;
                g_tile_rdy[tile]  = 0;
            }
            int a = atomicAdd(&g_all_done, 1);
            if (a == N_MTILES * N_NTILES - 1) {
                g_all_done = 0;
                g_w_rdy    = 0;
            }
        }
    }
}

// ================= launcher =================
extern "C" void kernel_launch(void* const* d_in, const int* in_sizes, int n_in,
                              void* d_out, int out_size) {
    const float* x        = (const float*)d_in[0];
    const float* base_w   = (const float*)d_in[1];
    const float* base_b   = (const float*)d_in[2];
    const float* spline_w = (const float*)d_in[3];
    float* out = (float*)d_out;

    (void)in_sizes; (void)n_in; (void)out_size;

    cudaFuncSetAttribute(kan_fused, cudaFuncAttributeMaxDynamicSharedMemorySize,
                         SMEM_TOTAL);
    kan_fused<<<OUT_FEAT + N_MTILES * GRP, 256, SMEM_TOTAL>>>(
        x, base_w, spline_w, base_b, out);
}

// round 16
// speedup vs baseline: 1.3423x; 1.3423x over previous
#include <cuda_runtime.h>
#include <cuda_fp16.h>

// ---------------- problem constants ----------------
#define BATCH    8192
#define IN_FEAT  512
#define OUT_FEAT 512
#define GK       13                       // GRID_SIZE + K
#define KTOT     (IN_FEAT + IN_FEAT*GK)   // 7168
#define ROWBYTES (KTOT * 2)               // 14336 bytes per fp16 row
#define KCHUNK   64                       // fp16 elems per stage chunk = 128B
#define NCHUNKS  (KTOT / KCHUNK)          // 112
#define TILE_M   128
#define TILE_N   128
#define STAGES   3

// k' layout (permuted, transparent to the GEMM):
//   k' in [0,512)     -> silu(x_i),           i = k'
//   k' in [512,7168)  -> basis_g(x_i), g = (k'-512)/512, i = (k'-512)%512
// g_wk uses the identical permutation, so the dot product is unchanged.

// ---------------- scratch (device globals; no allocation allowed) ------
__device__ __half g_act[(size_t)BATCH * KTOT];     // 117 MB activation matrix
__device__ __half g_wk [(size_t)OUT_FEAT * KTOT];  // 7.3 MB packed weights

// ---------------- helpers ----------------
__device__ __forceinline__ unsigned smem_u32(const void* p) {
    unsigned a;
    asm("{ .reg .u64 t; cvta.to.shared.u64 t, %1; cvt.u32.u64 %0, t; }"
        : "=r"(a) : "l"(p));
    return a;
}
__device__ __forceinline__ void cp16(unsigned saddr, const void* gaddr) {
    asm volatile("cp.async.cg.shared.global [%0], [%1], 16;"
                 :: "r"(saddr), "l"(gaddr));
}
__device__ __forceinline__ void cp_commit() {
    asm volatile("cp.async.commit_group;");
}
template <int N>
__device__ __forceinline__ void cp_wait() {
    asm volatile("cp.async.wait_group %0;" :: "n"(N));
}
__device__ __forceinline__ void ldx4(unsigned* r, unsigned addr) {
    asm volatile("ldmatrix.sync.aligned.m8n8.x4.shared.b16 {%0,%1,%2,%3}, [%4];"
                 : "=r"(r[0]), "=r"(r[1]), "=r"(r[2]), "=r"(r[3]) : "r"(addr));
}
__device__ __forceinline__ void mma16816(float* d, const unsigned* a,
                                         unsigned b0, unsigned b1) {
    asm volatile(
        "mma.sync.aligned.m16n8k16.row.col.f32.f16.f16.f32 "
        "{%0,%1,%2,%3}, {%4,%5,%6,%7}, {%8,%9}, {%0,%1,%2,%3};"
        : "+f"(d[0]), "+f"(d[1]), "+f"(d[2]), "+f"(d[3])
        : "r"(a[0]), "r"(a[1]), "r"(a[2]), "r"(a[3]), "r"(b0), "r"(b1));
}

// ========= kernel 0: merged prep =========
// blocks [0, 512): pack one weight row o (permuted g-major spline)
// blocks [512, 512 + 4096): build TWO activation rows via smem scatter
__global__ void __launch_bounds__(256)
kan_prep(const float* __restrict__ x,
         const float* __restrict__ base_w,
         const float* __restrict__ spline_w) {
    __shared__ __half s[2 * KTOT];         // 28672 B
    int tid = threadIdx.x;

    if (blockIdx.x < OUT_FEAT) {
        // ---- weight branch: transpose spline row to g-major ----
        int o = blockIdx.x;
        const float* bw = base_w + (size_t)o * IN_FEAT;
        __half* dstb = g_wk + (size_t)o * KTOT;
#pragma unroll
        for (int i = tid; i < IN_FEAT; i += 256)
            dstb[i] = __float2half_rn(bw[i]);

        const float* sw = spline_w + (size_t)o * (IN_FEAT * GK);
        for (int idx = tid; idx < IN_FEAT * GK; idx += 256) {
            int i = idx / GK, g = idx % GK;    // coalesced read
            s[i * 14 + g] = __float2half_rn(sw[idx]);
        }
        __syncthreads();

        __half* dsts = dstb + IN_FEAT;
        for (int idx = tid; idx < IN_FEAT * GK; idx += 256) {
            int g = idx >> 9, i = idx & 511;   // k' = g*512 + i (coalesced write)
            dsts[idx] = s[i * 14 + g];
        }
        return;
    }

    // ---- activation branch: 2 rows per block, scatter nonzero bases ----
    int r0 = (blockIdx.x - OUT_FEAT) * 2;

    // phase 1: zero the 28 KB row image
    int4* z = (int4*)s;
#pragma unroll
    for (int k = 0; k < 7; ++k)
        z[tid + k * 256] = make_int4(0, 0, 0, 0);
    __syncthreads();

    // phase 2: each thread computes 4 consecutive x elems of one row
    int row = tid >> 7;                    // 0..1
    int i0  = (tid & 127) << 2;            // 0..508
    float4 xv = *(const float4*)(x + (size_t)(r0 + row) * IN_FEAT + i0);
    __half* srow = s + row * KTOT;
    float xs[4] = { xv.x, xv.y, xv.z, xv.w };
#pragma unroll
    for (int e = 0; e < 4; ++e) {
        float v = xs[e];
        srow[i0 + e] = __float2half_rn(v / (1.0f + __expf(-v)));   // silu
        float t = (v + 3.2f) * 2.5f;       // knots -3.2 + 0.4j
        if (t >= 0.0f && t < 16.0f) {
            int j = (int)t;
            float u  = t - (float)j;
            float um = 1.0f - u;
            float u2 = u * u, u3 = u2 * u;
            float um3 = um * um * um;
            const float c6 = 1.0f / 6.0f;
            float wv[4];
            wv[0] = um3 * c6;
            wv[1] = (3.0f * u3 - 6.0f * u2 + 4.0f) * c6;
            wv[2] = (-3.0f * u3 + 3.0f * u2 + 3.0f * u + 1.0f) * c6;
            wv[3] = u3 * c6;
            int g0 = j - 3;
#pragma unroll
            for (int d = 0; d < 4; ++d) {
                int g = g0 + d;
                if (g >= 0 && g < GK)      // reference truncates edge bases
                    srow[IN_FEAT + (g << 9) + i0 + e] = __float2half_rn(wv[d]);
            }
        }
    }
    __syncthreads();

    // phase 3: coalesced copy-out (rows r0, r0+1 contiguous in g_act)
    const int4* src = (const int4*)s;
    int4* dst = (int4*)(g_act + (size_t)r0 * KTOT);
#pragma unroll
    for (int k = 0; k < 7; ++k)
        dst[tid + k * 256] = src[tid + k * 256];
}

// ================= kernel 1: fp16 mma.sync GEMM + bias =================
// C[8192,512] = Act[8192,7168] * Wk[512,7168]^T + bias
// CTA 128x128, 4 warps of 64x64, 3-stage cp.async ring, 2 CTAs/SM.
// (Best measured config: 183.6 us in R12.)
#define A_BYTES     (TILE_M * KCHUNK * 2)        // 16384
#define B_BYTES     (TILE_N * KCHUNK * 2)        // 16384
#define STAGE_BYTES (A_BYTES + B_BYTES)          // 32768
#define SMEM_TOTAL  (STAGES * STAGE_BYTES)       // 98304

__global__ void __launch_bounds__(128, 2)
kan_gemm(const float* __restrict__ bias, float* __restrict__ out) {
    extern __shared__ char smem[];
    unsigned sb = smem_u32(smem);
    int tid  = threadIdx.x;
    int w    = tid >> 5;
    int lane = tid & 31;
    int wm   = w >> 1;          // 0..1  (M direction, 64 rows each)
    int wn   = w & 1;           // 0..1  (N direction, 64 cols each)

    int m_base = (blockIdx.x >> 2) * TILE_M;
    int n_base = (blockIdx.x & 3) * TILE_N;

    // ---- cp.async loader precompute ----
    // 1024 16B-groups per matrix per stage; 128 threads -> 8 groups each.
    // row = (tid>>3) + q*16, c8 = tid&7; (row & 7) invariant in q.
    int  row0 = tid >> 3;                 // 0..15
    int  c8   = tid & 7;
    unsigned so = (unsigned)((row0 << 7) + (((unsigned)c8 ^ (row0 & 7)) << 4));
    const char* gA = (const char*)g_act + (size_t)(m_base + row0) * ROWBYTES + c8 * 16;
    const char* gB = (const char*)g_wk  + (size_t)(n_base + row0) * ROWBYTES + c8 * 16;

    // ---- ldmatrix per-lane precompute ----
    int lrow = lane & 15;
    unsigned lh = (unsigned)(lane >> 4);
    unsigned arow[4], abit[4], brow[4], bbit[4];
#pragma unroll
    for (int mt = 0; mt < 4; ++mt) {
        int r = wm * 64 + mt * 16 + lrow;
        arow[mt] = (unsigned)(r << 7);
        abit[mt] = (unsigned)(r & 7);
    }
#pragma unroll
    for (int bt = 0; bt < 4; ++bt) {
        int r = wn * 64 + bt * 16 + lrow;
        brow[bt] = (unsigned)(r << 7);
        bbit[bt] = (unsigned)(r & 7);
    }

    float acc[4][8][4];
#pragma unroll
    for (int mt = 0; mt < 4; ++mt)
#pragma unroll
        for (int nt = 0; nt < 8; ++nt)
#pragma unroll
            for (int e = 0; e < 4; ++e) acc[mt][nt][e] = 0.0f;

    // ---- prologue: issue chunks 0 and 1 into stages 0 and 1 ----
#pragma unroll
    for (int p = 0; p < 2; ++p) {
        unsigned base = sb + p * STAGE_BYTES;
        size_t koff = (size_t)p * 128;
#pragma unroll
        for (int q = 0; q < 8; ++q)
            cp16(base + so + q * 2048, gA + (size_t)q * 16 * ROWBYTES + koff);
#pragma unroll
        for (int q = 0; q < 8; ++q)
            cp16(base + A_BYTES + so + q * 2048, gB + (size_t)q * 16 * ROWBYTES + koff);
        cp_commit();
    }

    int s_cur = 0;   // stage of chunk c
    int s_nxt = 2;   // stage of chunk c+2 (write target)
    for (int c = 0; c < NCHUNKS; ++c) {
        if (c < NCHUNKS - 1) cp_wait<1>(); else cp_wait<0>();
        __syncthreads();   // all warps done with the stage about to be refilled

        if (c + 2 < NCHUNKS) {
            unsigned base = sb + s_nxt * STAGE_BYTES;
            size_t koff = (size_t)(c + 2) * 128;
#pragma unroll
            for (int q = 0; q < 8; ++q)
                cp16(base + so + q * 2048, gA + (size_t)q * 16 * ROWBYTES + koff);
#pragma unroll
            for (int q = 0; q < 8; ++q)
                cp16(base + A_BYTES + so + q * 2048, gB + (size_t)q * 16 * ROWBYTES + koff);
            cp_commit();
        }

        unsigned Ab = sb + s_cur * STAGE_BYTES;
        unsigned Bb = Ab + A_BYTES;
#pragma unroll
        for (int kt = 0; kt < 4; ++kt) {
            unsigned kc8 = (unsigned)(kt * 2) + lh;
            unsigned af[4][4];
#pragma unroll
            for (int mt = 0; mt < 4; ++mt)
                ldx4(af[mt], Ab + arow[mt] + ((kc8 ^ abit[mt]) << 4));
            unsigned bf[4][4];
#pragma unroll
            for (int bt = 0; bt < 4; ++bt)
                ldx4(bf[bt], Bb + brow[bt] + ((kc8 ^ bbit[bt]) << 4));
#pragma unroll
            for (int mt = 0; mt < 4; ++mt)
#pragma unroll
                for (int nt = 0; nt < 8; ++nt)
                    mma16816(acc[mt][nt], af[mt],
                             bf[nt >> 1][nt & 1], bf[nt >> 1][(nt & 1) + 2]);
        }

        s_cur = (s_cur == STAGES - 1) ? 0 : s_cur + 1;
        s_nxt = (s_nxt == STAGES - 1) ? 0 : s_nxt + 1;
    }

    // ---- epilogue: bias add + store (f32) ----
    int r0base = m_base + wm * 64 + (lane >> 2);
    int colb   = n_base + wn * 64 + ((lane & 3) << 1);
    float2 bs[8];
#pragma unroll
    for (int nt = 0; nt < 8; ++nt)
        bs[nt] = *(const float2*)(bias + colb + nt * 8);
#pragma unroll
    for (int mt = 0; mt < 4; ++mt) {
        int r0 = r0base + mt * 16;
        int r1 = r0 + 8;
#pragma unroll
        for (int nt = 0; nt < 8; ++nt) {
            int col = colb + nt * 8;
            float2 v0 = { acc[mt][nt][0] + bs[nt].x, acc[mt][nt][1] + bs[nt].y };
            float2 v1 = { acc[mt][nt][2] + bs[nt].x, acc[mt][nt][3] + bs[nt].y };
            *(float2*)(out + (size_t)r0 * OUT_FEAT + col) = v0;
            *(float2*)(out + (size_t)r1 * OUT_FEAT + col) = v1;
        }
    }
}

// ================= launcher =================
extern "C" void kernel_launch(void* const* d_in, const int* in_sizes, int n_in,
                              void* d_out, int out_size) {
    const float* x        = (const float*)d_in[0];
    const float* base_w   = (const float*)d_in[1];
    const float* base_b   = (const float*)d_in[2];
    const float* spline_w = (const float*)d_in[3];
    float* out = (float*)d_out;

    (void)in_sizes; (void)n_in; (void)out_size;

    kan_prep<<<OUT_FEAT + BATCH / 2, 256>>>(x, base_w, spline_w);

    cudaFuncSetAttribute(kan_gemm, cudaFuncAttributeMaxDynamicSharedMemorySize,
                         SMEM_TOTAL);
    kan_gemm<<<(BATCH / TILE_M) * (OUT_FEAT / TILE_N), 128, SMEM_TOTAL>>>(base_b, out);
}